// round 13
// baseline (speedup 1.0000x reference)
#include <cuda_runtime.h>
#include <cuda_fp16.h>
#include <cstdint>
#include <cstddef>

// ---------------- configuration ----------------
#define MAXB  65536
#define MT    128           // CTA rows
#define NT    64            // CTA cols per chunk
#define KB    64            // k-block (elements)
#define KPADW 36            // fp16 tile: padded u32 words per row (32 data + 4 pad)
#define ROWB  (KPADW * 4)   // 144 bytes
#define I8W   20            // s8 tile: padded u32 words per row (16 data + 4 pad)
#define I8ROWB (I8W * 4)    // 80 bytes
// stage layout (bytes, within one stage)
#define OFF_A16 0
#define OFF_A8  (MT * ROWB)                    // 18432
#define OFF_WMH (OFF_A8 + MT * I8ROWB)         // 28672
#define OFF_WSH (OFF_WMH + NT * ROWB)          // 37888
#define OFF_WML (OFF_WSH + NT * ROWB)          // 47104
#define OFF_WSL (OFF_WML + NT * I8ROWB)        // 52224
#define STAGE_BYTES (OFF_WSL + NT * I8ROWB)    // 57344
#define SM_BIAS 0
#define SM_RED  4096
#define SM_TILE 8192
#define SMEM_TOTAL (SM_TILE + 2 * STAGE_BYTES) // 122880
// int8 scales: a8 = round(a*SA), wl8 = round(wl*SW); correction = acc/(SA*SW)
#define SA_Q 32.0f
#define SW_Q (127.0f * 65536.0f)
#define LOI_INV (1.0f / (SA_Q * SW_Q))
#define NSPLIT 2            // N-axis split (halves of H per CTA)

// partial per-row coefficients: [set(x=0,y=1)][half][row][S1,S2,S3,S4]
__device__ float g_coefp[2][NSPLIT][MAXB][4];
// fp16 hi data: A [set]; W hi [set][mu=0,sg=1]
__device__ __align__(16) __half g_A16[2][(size_t)32768 * 512];
__device__ __align__(16) __half g_Wh16[2][2][512 * 512];
// s8 data: A (quantized full value) [set]; W lo residual (quantized) [set][mu,sg]
__device__ __align__(16) int8_t g_A8[2][(size_t)32768 * 512];
__device__ __align__(16) int8_t g_Wl8[2][2][512 * 512];

// ---------------- helpers ----------------
__device__ __forceinline__ void cpa16(uint32_t dst, const void* src) {
    asm volatile("cp.async.cg.shared.global [%0], [%1], 16;" :: "r"(dst), "l"(src));
}
__device__ __forceinline__ uint32_t smem_u32(const void* p) {
    uint32_t a;
    asm("{ .reg .u64 t; cvta.to.shared.u64 t, %1; cvt.u32.u64 %0, t; }" : "=r"(a) : "l"(p));
    return a;
}
__device__ __forceinline__ void mma_f16(float* d, const uint32_t* a, const uint32_t* b) {
    asm volatile(
        "mma.sync.aligned.m16n8k16.row.col.f32.f16.f16.f32 "
        "{%0,%1,%2,%3}, {%4,%5,%6,%7}, {%8,%9}, {%0,%1,%2,%3};"
        : "+f"(d[0]), "+f"(d[1]), "+f"(d[2]), "+f"(d[3])
        : "r"(a[0]), "r"(a[1]), "r"(a[2]), "r"(a[3]), "r"(b[0]), "r"(b[1]));
}
__device__ __forceinline__ void mma_s8(int* d, const uint32_t* a, const uint32_t* b) {
    asm volatile(
        "mma.sync.aligned.m16n8k32.row.col.s32.s8.s8.s32 "
        "{%0,%1,%2,%3}, {%4,%5,%6,%7}, {%8,%9}, {%0,%1,%2,%3};"
        : "+r"(d[0]), "+r"(d[1]), "+r"(d[2]), "+r"(d[3])
        : "r"(a[0]), "r"(a[1]), "r"(a[2]), "r"(a[3]), "r"(b[0]), "r"(b[1]));
}
__device__ __forceinline__ uint8_t to_s8(float v) {
    int q = __float2int_rn(v);
    q = max(-127, min(127, q));
    return (uint8_t)(q & 0xff);
}

// ---------------- prep (fused) ----------------
__global__ void split_a_all(const float* __restrict__ x, const float* __restrict__ y, int n4) {
    int i = blockIdx.x * blockDim.x + threadIdx.x;
    if (i >= 2 * n4) return;
    int set = i >= n4;
    int j = set ? (i - n4) : i;
    const float* src = set ? y : x;
    float4 a = ((const float4*)src)[j];
    __half2 h01 = __halves2half2(__float2half_rn(a.x), __float2half_rn(a.y));
    __half2 h23 = __halves2half2(__float2half_rn(a.z), __float2half_rn(a.w));
    __half2* Hp = (__half2*)g_A16[set];
    Hp[2 * j] = h01; Hp[2 * j + 1] = h23;
    uint32_t q = (uint32_t)to_s8(a.x * SA_Q) | ((uint32_t)to_s8(a.y * SA_Q) << 8)
               | ((uint32_t)to_s8(a.z * SA_Q) << 16) | ((uint32_t)to_s8(a.w * SA_Q) << 24);
    ((uint32_t*)g_A8[set])[j] = q;
}
__global__ void split_w_all(const float* __restrict__ Wmx, const float* __restrict__ Wsx,
                            const float* __restrict__ Wmy, const float* __restrict__ Wsy,
                            int w4) {
    int i = blockIdx.x * blockDim.x + threadIdx.x;
    if (i >= 4 * w4) return;
    int which = i / w4;          // 0=Wmx 1=Wsx 2=Wmy 3=Wsy
    int j = i - which * w4;
    int set = which >> 1;
    int mat = which & 1;
    const float* src = (which == 0) ? Wmx : (which == 1) ? Wsx : (which == 2) ? Wmy : Wsy;
    float4 a = ((const float4*)src)[j];
    __half h0 = __float2half_rn(a.x);
    __half h1 = __float2half_rn(a.y);
    __half h2 = __float2half_rn(a.z);
    __half h3 = __float2half_rn(a.w);
    __half2* Hp = (__half2*)g_Wh16[set][mat];
    Hp[2 * j] = __halves2half2(h0, h1); Hp[2 * j + 1] = __halves2half2(h2, h3);
    uint32_t q = (uint32_t)to_s8((a.x - __half2float(h0)) * SW_Q)
               | ((uint32_t)to_s8((a.y - __half2float(h1)) * SW_Q) << 8)
               | ((uint32_t)to_s8((a.z - __half2float(h2)) * SW_Q) << 16)
               | ((uint32_t)to_s8((a.w - __half2float(h3)) * SW_Q) << 24);
    ((uint32_t*)g_Wl8[set][mat])[j] = q;
}

// ---------------- fused mixed fp16/int8 mma GEMM + NLL coefficient kernel ----------------
// grid = (B/MT, 2 sets, NSPLIT halves); 256 threads = 8 warps as 4(M) x 2(N); warp tile 32x32.
struct Srcs {
    const __half* a16; const int8_t* a8;
    const __half* wh[2];      // mu, sg hi
    const int8_t* wl[2];      // mu, sg lo (s8 x SW_Q)
};

__device__ __forceinline__ void issue_loads(uint32_t base, const Srcs& S,
                                            int r0, int n0, int kb, int IN, int tid)
{
    // A16 tile: 128 rows x 8 chunks (16B)
#pragma unroll
    for (int it = 0; it < 4; ++it) {
        int t = tid + it * 256;
        int r = t >> 3, c = t & 7;
        cpa16(base + OFF_A16 + r * ROWB + c * 16,
              S.a16 + (size_t)(r0 + r) * IN + kb + c * 8);
    }
    // A8 tile: 128 rows x 4 chunks
#pragma unroll
    for (int it = 0; it < 2; ++it) {
        int t = tid + it * 256;
        int r = t >> 2, c = t & 3;
        cpa16(base + OFF_A8 + r * I8ROWB + c * 16,
              S.a8 + (size_t)(r0 + r) * IN + kb + c * 16);
    }
    // W hi tiles: 2 x (64 rows x 8 chunks)
#pragma unroll
    for (int it = 0; it < 4; ++it) {
        int t = tid + it * 256;
        int tt = t >> 9;
        int u = t & 511;
        int r = u >> 3, c = u & 7;
        cpa16(base + OFF_WMH + tt * (NT * ROWB) + r * ROWB + c * 16,
              S.wh[tt] + (size_t)(n0 + r) * IN + kb + c * 8);
    }
    // W lo s8 tiles: 2 x (64 rows x 4 chunks)
#pragma unroll
    for (int it = 0; it < 2; ++it) {
        int t = tid + it * 256;
        int tt = t >> 8;
        int u = t & 255;
        int r = u >> 2, c = u & 3;
        cpa16(base + OFF_WML + tt * (NT * I8ROWB) + r * I8ROWB + c * 16,
              S.wl[tt] + (size_t)(n0 + r) * IN + kb + c * 16);
    }
    asm volatile("cp.async.commit_group;" ::: "memory");
}

__global__ __launch_bounds__(256, 1)
void coef_mma_kernel(const float* __restrict__ bmx, const float* __restrict__ bsx,
                     const float* __restrict__ bmy, const float* __restrict__ bsy,
                     int B, int IN, int H)
{
    extern __shared__ char smem[];
    const int set  = blockIdx.y;
    const int half = blockIdx.z;
    const int r0   = blockIdx.x * MT;
    const int tid  = threadIdx.x;
    const int wid  = tid >> 5;
    const int lane = tid & 31;
    const int wm   = wid & 3;       // M stripe (32 rows)
    const int wn   = wid >> 2;      // N stripe (32 cols)
    const int g    = lane >> 2;     // group id
    const int tg   = lane & 3;      // thread in group
    const uint32_t sb = smem_u32(smem);

    const int Hh  = H / NSPLIT;           // cols handled by this CTA (256)
    const int hb  = half * Hh;            // global col base

    Srcs S;
    S.a16 = g_A16[set];
    S.a8  = g_A8[set];
    S.wh[0] = g_Wh16[set][0];
    S.wh[1] = g_Wh16[set][1];
    S.wl[0] = g_Wl8[set][0];
    S.wl[1] = g_Wl8[set][1];

    // bias preload for this half: [0,Hh) mu, [Hh,2Hh) sg
    {
        const float* bmu = set ? bmy : bmx;
        const float* bsg = set ? bsy : bsx;
        float* bias_s = (float*)(smem + SM_BIAS);
        for (int t = tid; t < Hh; t += 256) {
            bias_s[t] = bmu[hb + t];
            bias_s[Hh + t] = bsg[hb + t];
        }
    }
    __syncthreads();
    const float* bias_s = (const float*)(smem + SM_BIAS);

    float s1[4] = {0.f, 0.f, 0.f, 0.f};
    float s2[4] = {0.f, 0.f, 0.f, 0.f};
    float s3[4] = {0.f, 0.f, 0.f, 0.f};
    float s4[4] = {0.f, 0.f, 0.f, 0.f};

    const int nkc = IN / KB;   // 8
    const int nnh = Hh / NT;   // 4

    for (int nh = 0; nh < nnh; ++nh) {
        const int n0 = hb + nh * NT;
        float accMuH[2][4][4], accSgH[2][4][4];
        int   accMuL[2][4][4], accSgL[2][4][4];
#pragma unroll
        for (int i = 0; i < 2; ++i)
#pragma unroll
            for (int j = 0; j < 4; ++j)
#pragma unroll
                for (int c = 0; c < 4; ++c) {
                    accMuH[i][j][c] = 0.f; accSgH[i][j][c] = 0.f;
                    accMuL[i][j][c] = 0;   accSgL[i][j][c] = 0;
                }

        issue_loads(sb + SM_TILE, S, r0, n0, 0, IN, tid);

        for (int kc = 0; kc < nkc; ++kc) {
            if (kc + 1 < nkc) {
                issue_loads(sb + SM_TILE + ((kc + 1) & 1) * STAGE_BYTES,
                            S, r0, n0, (kc + 1) * KB, IN, tid);
                asm volatile("cp.async.wait_group 1;" ::: "memory");
            } else {
                asm volatile("cp.async.wait_group 0;" ::: "memory");
            }
            __syncthreads();

            const char* stg = smem + SM_TILE + (kc & 1) * STAGE_BYTES;
            const uint32_t* A16s = (const uint32_t*)(stg + OFF_A16);
            const uint32_t* A8s  = (const uint32_t*)(stg + OFF_A8);
            const uint32_t* WMHs = (const uint32_t*)(stg + OFF_WMH);
            const uint32_t* WSHs = (const uint32_t*)(stg + OFF_WSH);
            const uint32_t* WMLs = (const uint32_t*)(stg + OFF_WML);
            const uint32_t* WSLs = (const uint32_t*)(stg + OFF_WSL);

#pragma unroll
            for (int kblk = 0; kblk < 2; ++kblk) {           // two k32 blocks per kc
                // fp16 A fragments for the two k16 steps of this k32 block
                uint32_t ah[2][2][4];                        // [ks2][i][reg]
#pragma unroll
                for (int ks2 = 0; ks2 < 2; ++ks2) {
                    int kw = kblk * 16 + ks2 * 8;
#pragma unroll
                    for (int i = 0; i < 2; ++i) {
                        int mr = (wm * 32 + i * 16 + g) * KPADW + kw + tg;
                        ah[ks2][i][0] = A16s[mr];
                        ah[ks2][i][1] = A16s[mr + 8 * KPADW];
                        ah[ks2][i][2] = A16s[mr + 4];
                        ah[ks2][i][3] = A16s[mr + 4 + 8 * KPADW];
                    }
                }
                // s8 A fragments (k32)
                uint32_t a8[2][4];
#pragma unroll
                for (int i = 0; i < 2; ++i) {
                    int mr = (wm * 32 + i * 16 + g) * I8W + kblk * 8 + tg;
                    a8[i][0] = A8s[mr];
                    a8[i][1] = A8s[mr + 8 * I8W];
                    a8[i][2] = A8s[mr + 4];
                    a8[i][3] = A8s[mr + 4 + 8 * I8W];
                }
#pragma unroll
                for (int j = 0; j < 4; ++j) {
                    int o16 = (wn * 32 + j * 8 + g) * KPADW + kblk * 16 + tg;
                    uint32_t bmh0[2] = { WMHs[o16],     WMHs[o16 + 4] };
                    uint32_t bmh1[2] = { WMHs[o16 + 8], WMHs[o16 + 12] };
                    uint32_t bsh0[2] = { WSHs[o16],     WSHs[o16 + 4] };
                    uint32_t bsh1[2] = { WSHs[o16 + 8], WSHs[o16 + 12] };
                    int o8 = (wn * 32 + j * 8 + g) * I8W + kblk * 8 + tg;
                    uint32_t bml[2] = { WMLs[o8], WMLs[o8 + 4] };
                    uint32_t bsl[2] = { WSLs[o8], WSLs[o8 + 4] };
#pragma unroll
                    for (int i = 0; i < 2; ++i) {
                        mma_f16(accMuH[i][j], ah[0][i], bmh0);
                        mma_f16(accMuH[i][j], ah[1][i], bmh1);
                        mma_f16(accSgH[i][j], ah[0][i], bsh0);
                        mma_f16(accSgH[i][j], ah[1][i], bsh1);
                        mma_s8(accMuL[i][j], a8[i], bml);
                        mma_s8(accSgL[i][j], a8[i], bsl);
                    }
                }
            }
            __syncthreads();
        }

        // epilogue: combine hi+lo, bias + exp/log/rcp + NLL partial sums
#pragma unroll
        for (int i = 0; i < 2; ++i) {
#pragma unroll
            for (int j = 0; j < 4; ++j) {
#pragma unroll
                for (int c = 0; c < 4; ++c) {
                    int h = nh * NT + wn * 32 + j * 8 + 2 * tg + (c & 1);  // local within half
                    float m = accMuH[i][j][c] + (float)accMuL[i][j][c] * LOI_INV + bias_s[h];
                    float v = expf(accSgH[i][j][c] + (float)accSgL[i][j][c] * LOI_INV + bias_s[Hh + h]);
                    v = fmaxf(v, 1e-6f);        // GaussianNLLLoss eps clamp
                    float lg = logf(v);
                    float rc = 1.0f / v;
                    int slot = i * 2 + (c >> 1);
                    s1[slot] += lg;
                    s2[slot] += rc;
                    s3[slot] += m * rc;
                    s4[slot] += m * m * rc;
                }
            }
        }
    }

    // reduce over the 4 lanes of each group (cols), then across the 2 N-warps
#pragma unroll
    for (int slot = 0; slot < 4; ++slot) {
        s1[slot] += __shfl_xor_sync(0xffffffffu, s1[slot], 1);
        s1[slot] += __shfl_xor_sync(0xffffffffu, s1[slot], 2);
        s2[slot] += __shfl_xor_sync(0xffffffffu, s2[slot], 1);
        s2[slot] += __shfl_xor_sync(0xffffffffu, s2[slot], 2);
        s3[slot] += __shfl_xor_sync(0xffffffffu, s3[slot], 1);
        s3[slot] += __shfl_xor_sync(0xffffffffu, s3[slot], 2);
        s4[slot] += __shfl_xor_sync(0xffffffffu, s4[slot], 1);
        s4[slot] += __shfl_xor_sync(0xffffffffu, s4[slot], 2);
    }
    float (*red)[4] = (float(*)[4])(smem + SM_RED);
    __syncthreads();
    if (wn == 0 && tg == 0) {
#pragma unroll
        for (int slot = 0; slot < 4; ++slot) {
            int row = wm * 32 + (slot >> 1) * 16 + (slot & 1) * 8 + g;
            red[row][0] = s1[slot]; red[row][1] = s2[slot];
            red[row][2] = s3[slot]; red[row][3] = s4[slot];
        }
    }
    __syncthreads();
    if (wn == 1 && tg == 0) {
#pragma unroll
        for (int slot = 0; slot < 4; ++slot) {
            int row = wm * 32 + (slot >> 1) * 16 + (slot & 1) * 8 + g;
            int grow = r0 + row;
            if (grow < B) {
                g_coefp[set][half][grow][0] = red[row][0] + s1[slot];
                g_coefp[set][half][grow][1] = red[row][1] + s2[slot];
                g_coefp[set][half][grow][2] = red[row][2] + s3[slot];
                g_coefp[set][half][grow][3] = red[row][3] + s4[slot];
            }
        }
    }
}

// ---------------- Threefry-2x32-20 (exact JAX schedule) ----------------
__device__ __forceinline__ void threefry(uint32_t k0, uint32_t k1,
                                         uint32_t x0, uint32_t x1,
                                         uint32_t& o0, uint32_t& o1) {
    uint32_t ks2 = k0 ^ k1 ^ 0x1BD11BDAu;
    x0 += k0; x1 += k1;
#define TF_RND(r) { x0 += x1; x1 = (x1 << (r)) | (x1 >> (32 - (r))); x1 ^= x0; }
    TF_RND(13) TF_RND(15) TF_RND(26) TF_RND(6)
    x0 += k1;  x1 += ks2 + 1u;
    TF_RND(17) TF_RND(29) TF_RND(16) TF_RND(24)
    x0 += ks2; x1 += k0 + 2u;
    TF_RND(13) TF_RND(15) TF_RND(26) TF_RND(6)
    x0 += k0;  x1 += k1 + 3u;
    TF_RND(17) TF_RND(29) TF_RND(16) TF_RND(24)
    x0 += k1;  x1 += ks2 + 4u;
    TF_RND(13) TF_RND(15) TF_RND(26) TF_RND(6)
    x0 += ks2; x1 += k0 + 5u;
#undef TF_RND
    o0 = x0; o1 = x1;
}

__device__ __forceinline__ float bits_to_unit(uint32_t bits) {
    float f = __uint_as_float((bits >> 9) | 0x3f800000u) - 1.0f;
    return fmaxf(f, 0.0f);
}

// ---------------- per-row rejection sampling (JAX threefry, partitionable mode) ----------------
__global__ void sample_kernel(float* __restrict__ out, int B, float invH)
{
    int i = blockIdx.x * blockDim.x + threadIdx.x;
    if (i >= B) return;

    float s1x = g_coefp[0][0][i][0] + g_coefp[0][1][i][0];
    float s2x = g_coefp[0][0][i][1] + g_coefp[0][1][i][1];
    float s3x = g_coefp[0][0][i][2] + g_coefp[0][1][i][2];
    float s4x = g_coefp[0][0][i][3] + g_coefp[0][1][i][3];
    float s1y = g_coefp[1][0][i][0] + g_coefp[1][1][i][0];
    float s2y = g_coefp[1][0][i][1] + g_coefp[1][1][i][1];
    float s3y = g_coefp[1][0][i][2] + g_coefp[1][1][i][2];
    float s4y = g_coefp[1][0][i][3] + g_coefp[1][1][i][3];

    float ax = 0.5f * (s1x + s4x) * invH;
    float bxc = -s3x * invH;
    float cx = 0.5f * s2x * invH;
    float ay = 0.5f * (s1y + s4y) * invH;
    float byc = -s3y * invH;
    float cy = 0.5f * s2y * invH;

    uint32_t k0, k1;
    threefry(0u, 42u, 0u, (uint32_t)i, k0, k1);

    float xi = 0.0f;
    for (int it = 0; it < 4096; ++it) {
        uint32_t n0, n1, p0, p1, q0, q1;
        threefry(k0, k1, 0u, 0u, n0, n1);
        threefry(k0, k1, 0u, 1u, p0, p1);
        threefry(k0, k1, 0u, 2u, q0, q1);
        uint32_t ub0, ub1, xb0, xb1;
        threefry(p0, p1, 0u, 0u, ub0, ub1);
        threefry(q0, q1, 0u, 0u, xb0, xb1);
        float u  = bits_to_unit(ub0 ^ ub1);
        float x2 = bits_to_unit(xb0 ^ xb1);
        xi = 2.0f * x2 - 1.0f;

        float qx = fmaf(fmaf(cx, xi, bxc), xi, ax);
        float qy = fmaf(fmaf(cy, xi, byc), xi, ay);
        float q  = qx * qy;

        k0 = n0; k1 = n1;
        if (u >= q) break;
    }
    out[i] = fminf(fmaxf(xi, 1e-5f), 10.0f);
}

// ---------------- launch ----------------
extern "C" void kernel_launch(void* const* d_in, const int* in_sizes, int n_in,
                              void* d_out, int out_size)
{
    const float* x   = (const float*)d_in[0];
    const float* y   = (const float*)d_in[1];
    const float* Wmx = (const float*)d_in[2];
    const float* bmx = (const float*)d_in[3];
    const float* Wsx = (const float*)d_in[4];
    const float* bsx = (const float*)d_in[5];
    const float* Wmy = (const float*)d_in[6];
    const float* bmy = (const float*)d_in[7];
    const float* Wsy = (const float*)d_in[8];
    const float* bsy = (const float*)d_in[9];

    int H  = in_sizes[3];
    int IN = in_sizes[2] / H;
    int B  = in_sizes[0] / IN;

    int a4 = (B * IN) / 4;
    split_a_all<<<(2 * a4 + 255) / 256, 256>>>(x, y, a4);
    int w4 = (H * IN) / 4;
    split_w_all<<<(4 * w4 + 255) / 256, 256>>>(Wmx, Wsx, Wmy, Wsy, w4);

    cudaFuncSetAttribute(coef_mma_kernel, cudaFuncAttributeMaxDynamicSharedMemorySize, SMEM_TOTAL);
    dim3 grid(B / MT, 2, NSPLIT);
    coef_mma_kernel<<<grid, 256, SMEM_TOTAL>>>(bmx, bsx, bmy, bsy, B, IN, H);

    int thr = 256;
    sample_kernel<<<(B + thr - 1) / thr, thr>>>((float*)d_out, B, 1.0f / (float)H);
}

// round 14
// speedup vs baseline: 1.7117x; 1.7117x over previous
#include <cuda_runtime.h>
#include <cuda_fp16.h>
#include <cstdint>
#include <cstddef>

// ---------------- configuration ----------------
#define MAXB  65536
#define MT    128           // CTA rows
#define NT    64            // CTA cols per chunk
#define KB    64            // k-block (fp16 elements)
#define KPADW 36            // padded u32 words per smem row (32 data + 4 pad)
#define ROWB  (KPADW * 4)   // 144 bytes
#define SA_BYTES (MT * ROWB)               // 18432 (A hi tile)
#define SWT_BYTES (NT * ROWB)              // 9216 per W tile
#define STAGE_BYTES (SA_BYTES + 4 * SWT_BYTES)   // 55296
#define SM_BIAS 0
#define SM_RED  4096
#define SM_TILE 8192
#define SMEM_TOTAL (SM_TILE + 2 * STAGE_BYTES)   // 118784
#define LO_SCALE 2048.0f
#define LO_INV   (1.0f / 2048.0f)
#define NSPLIT 2            // N-axis split (halves of H per CTA)

// partial per-row coefficients: [set(x=0,y=1)][half][row][S1,S2,S3,S4]
__device__ float g_coefp[2][NSPLIT][MAXB][4];
// fp16 data: A hi only [set]; W hi/lo [set][mu=0,sg=1][h=0,l=1]
__device__ __align__(16) __half g_A16[2][(size_t)32768 * 512];
__device__ __align__(16) __half g_W16[2][2][2][512 * 512];

// ---------------- helpers ----------------
__device__ __forceinline__ void cpa16(uint32_t dst, const void* src) {
    asm volatile("cp.async.cg.shared.global [%0], [%1], 16;" :: "r"(dst), "l"(src));
}
__device__ __forceinline__ uint32_t smem_u32(const void* p) {
    uint32_t a;
    asm("{ .reg .u64 t; cvta.to.shared.u64 t, %1; cvt.u32.u64 %0, t; }" : "=r"(a) : "l"(p));
    return a;
}
__device__ __forceinline__ void mma_f16(float* d, const uint32_t* a, const uint32_t* b) {
    asm volatile(
        "mma.sync.aligned.m16n8k16.row.col.f32.f16.f16.f32 "
        "{%0,%1,%2,%3}, {%4,%5,%6,%7}, {%8,%9}, {%0,%1,%2,%3};"
        : "+f"(d[0]), "+f"(d[1]), "+f"(d[2]), "+f"(d[3])
        : "r"(a[0]), "r"(a[1]), "r"(a[2]), "r"(a[3]), "r"(b[0]), "r"(b[1]));
}

// ---------------- prep: single fused split kernel ----------------
// index space: [0, 2*a4)           -> A fp16 conversion (x then y)
//              [2*a4, 2*a4 + 4*w4) -> W hi/lo split (Wmx, Wsx, Wmy, Wsy)
__global__ void split_all(const float* __restrict__ x, const float* __restrict__ y,
                          const float* __restrict__ Wmx, const float* __restrict__ Wsx,
                          const float* __restrict__ Wmy, const float* __restrict__ Wsy,
                          int a4, int w4)
{
    int i = blockIdx.x * blockDim.x + threadIdx.x;
    if (i < 2 * a4) {
        int set = i >= a4;
        int j = set ? (i - a4) : i;
        const float* src = set ? y : x;
        float4 a = ((const float4*)src)[j];
        __half2 h01 = __halves2half2(__float2half_rn(a.x), __float2half_rn(a.y));
        __half2 h23 = __halves2half2(__float2half_rn(a.z), __float2half_rn(a.w));
        __half2* Hp = (__half2*)g_A16[set];
        Hp[2 * j] = h01; Hp[2 * j + 1] = h23;
        return;
    }
    int t = i - 2 * a4;
    if (t >= 4 * w4) return;
    int which = t / w4;          // 0=Wmx 1=Wsx 2=Wmy 3=Wsy
    int j = t - which * w4;
    int set = which >> 1;
    int mat = which & 1;
    const float* src = (which == 0) ? Wmx : (which == 1) ? Wsx : (which == 2) ? Wmy : Wsy;
    float4 a = ((const float4*)src)[j];
    __half h0 = __float2half_rn(a.x);
    __half h1 = __float2half_rn(a.y);
    __half h2 = __float2half_rn(a.z);
    __half h3 = __float2half_rn(a.w);
    __half l0 = __float2half_rn((a.x - __half2float(h0)) * LO_SCALE);
    __half l1 = __float2half_rn((a.y - __half2float(h1)) * LO_SCALE);
    __half l2 = __float2half_rn((a.z - __half2float(h2)) * LO_SCALE);
    __half l3 = __float2half_rn((a.w - __half2float(h3)) * LO_SCALE);
    __half2* Hp = (__half2*)g_W16[set][mat][0];
    __half2* Lp = (__half2*)g_W16[set][mat][1];
    Hp[2 * j] = __halves2half2(h0, h1); Hp[2 * j + 1] = __halves2half2(h2, h3);
    Lp[2 * j] = __halves2half2(l0, l1); Lp[2 * j + 1] = __halves2half2(l2, l3);
}

// ---------------- fused fp16 2-product mma GEMM + NLL coefficient kernel ----------------
// grid = (B/MT, 2 sets, NSPLIT halves); 256 threads = 8 warps as 4(M) x 2(N); warp tile 32x32.
struct Srcs { const __half* a; const __half* w[4]; };

__device__ __forceinline__ void issue_loads(uint32_t base, const Srcs& S,
                                            int r0, int n0, int kb, int IN, int tid)
{
    // A hi tile: 128 rows x 8 chunks (16B)
#pragma unroll
    for (int it = 0; it < 4; ++it) {
        int t = tid + it * 256;
        int r = t >> 3, c = t & 7;
        cpa16(base + r * ROWB + c * 16,
              S.a + (size_t)(r0 + r) * IN + kb + c * 8);
    }
    // W tiles: 4 x (64 rows x 8 chunks)
#pragma unroll
    for (int it = 0; it < 8; ++it) {
        int t = tid + it * 256;
        int tt = t >> 9;                 // 0..3
        int u = t & 511;
        int r = u >> 3, c = u & 7;
        cpa16(base + SA_BYTES + tt * SWT_BYTES + r * ROWB + c * 16,
              S.w[tt] + (size_t)(n0 + r) * IN + kb + c * 8);
    }
    asm volatile("cp.async.commit_group;" ::: "memory");
}

__global__ __launch_bounds__(256, 1)
void coef_mma_kernel(const float* __restrict__ bmx, const float* __restrict__ bsx,
                     const float* __restrict__ bmy, const float* __restrict__ bsy,
                     int B, int IN, int H)
{
    extern __shared__ char smem[];
    const int set  = blockIdx.y;
    const int half = blockIdx.z;
    const int r0   = blockIdx.x * MT;
    const int tid  = threadIdx.x;
    const int wid  = tid >> 5;
    const int lane = tid & 31;
    const int wm   = wid & 3;       // M stripe (32 rows)
    const int wn   = wid >> 2;      // N stripe (32 cols)
    const int g    = lane >> 2;     // group id
    const int tg   = lane & 3;      // thread in group
    const uint32_t sb = smem_u32(smem);

    const int Hh  = H / NSPLIT;           // cols handled by this CTA (256)
    const int hb  = half * Hh;            // global col base

    Srcs S;
    S.a = g_A16[set];
    S.w[0] = g_W16[set][0][0];  // Wm hi
    S.w[1] = g_W16[set][0][1];  // Wm lo (x2048)
    S.w[2] = g_W16[set][1][0];  // Ws hi
    S.w[3] = g_W16[set][1][1];  // Ws lo (x2048)

    // bias preload for this half: [0,Hh) mu, [Hh,2Hh) sg
    {
        const float* bmu = set ? bmy : bmx;
        const float* bsg = set ? bsy : bsx;
        float* bias_s = (float*)(smem + SM_BIAS);
        for (int t = tid; t < Hh; t += 256) {
            bias_s[t] = bmu[hb + t];
            bias_s[Hh + t] = bsg[hb + t];
        }
    }
    __syncthreads();
    const float* bias_s = (const float*)(smem + SM_BIAS);

    float s1[4] = {0.f, 0.f, 0.f, 0.f};
    float s2[4] = {0.f, 0.f, 0.f, 0.f};
    float s3[4] = {0.f, 0.f, 0.f, 0.f};
    float s4[4] = {0.f, 0.f, 0.f, 0.f};

    const int nkc = IN / KB;   // 8
    const int nnh = Hh / NT;   // 4

    for (int nh = 0; nh < nnh; ++nh) {
        const int n0 = hb + nh * NT;
        float accMuH[2][4][4], accMuL[2][4][4], accSgH[2][4][4], accSgL[2][4][4];
#pragma unroll
        for (int i = 0; i < 2; ++i)
#pragma unroll
            for (int j = 0; j < 4; ++j)
#pragma unroll
                for (int c = 0; c < 4; ++c) {
                    accMuH[i][j][c] = 0.f; accMuL[i][j][c] = 0.f;
                    accSgH[i][j][c] = 0.f; accSgL[i][j][c] = 0.f;
                }

        issue_loads(sb + SM_TILE, S, r0, n0, 0, IN, tid);

        for (int kc = 0; kc < nkc; ++kc) {
            if (kc + 1 < nkc) {
                issue_loads(sb + SM_TILE + ((kc + 1) & 1) * STAGE_BYTES,
                            S, r0, n0, (kc + 1) * KB, IN, tid);
                asm volatile("cp.async.wait_group 1;" ::: "memory");
            } else {
                asm volatile("cp.async.wait_group 0;" ::: "memory");
            }
            __syncthreads();

            const uint32_t* Ath = (const uint32_t*)(smem + SM_TILE + (kc & 1) * STAGE_BYTES);
            const uint32_t* Wt  = Ath + SA_BYTES / 4;

#pragma unroll
            for (int ks = 0; ks < KB / 16; ++ks) {
                const int kw = ks * 8;             // u32 word offset within row
                uint32_t ah[2][4];
#pragma unroll
                for (int i = 0; i < 2; ++i) {
                    int mr = (wm * 32 + i * 16 + g) * KPADW + kw + tg;
                    ah[i][0] = Ath[mr];
                    ah[i][1] = Ath[mr + 8 * KPADW];
                    ah[i][2] = Ath[mr + 4];
                    ah[i][3] = Ath[mr + 4 + 8 * KPADW];
                }
#pragma unroll
                for (int j = 0; j < 4; ++j) {
                    int o = (wn * 32 + j * 8 + g) * KPADW + kw + tg;
                    uint32_t bmh[2] = { Wt[0 * (SWT_BYTES/4) + o], Wt[0 * (SWT_BYTES/4) + o + 4] };
                    uint32_t bml[2] = { Wt[1 * (SWT_BYTES/4) + o], Wt[1 * (SWT_BYTES/4) + o + 4] };
                    uint32_t bsh[2] = { Wt[2 * (SWT_BYTES/4) + o], Wt[2 * (SWT_BYTES/4) + o + 4] };
                    uint32_t bsl[2] = { Wt[3 * (SWT_BYTES/4) + o], Wt[3 * (SWT_BYTES/4) + o + 4] };
#pragma unroll
                    for (int i = 0; i < 2; ++i) {
                        mma_f16(accMuH[i][j], ah[i], bmh);
                        mma_f16(accMuL[i][j], ah[i], bml);
                        mma_f16(accSgH[i][j], ah[i], bsh);
                        mma_f16(accSgL[i][j], ah[i], bsl);
                    }
                }
            }
            __syncthreads();
        }

        // epilogue: combine hi+lo, bias + exp/log/rcp + NLL partial sums
#pragma unroll
        for (int i = 0; i < 2; ++i) {
#pragma unroll
            for (int j = 0; j < 4; ++j) {
#pragma unroll
                for (int c = 0; c < 4; ++c) {
                    int h = nh * NT + wn * 32 + j * 8 + 2 * tg + (c & 1);  // local within half
                    float m = accMuH[i][j][c] + accMuL[i][j][c] * LO_INV + bias_s[h];
                    float v = expf(accSgH[i][j][c] + accSgL[i][j][c] * LO_INV + bias_s[Hh + h]);
                    v = fmaxf(v, 1e-6f);        // GaussianNLLLoss eps clamp
                    float lg = logf(v);
                    float rc = 1.0f / v;
                    int slot = i * 2 + (c >> 1);
                    s1[slot] += lg;
                    s2[slot] += rc;
                    s3[slot] += m * rc;
                    s4[slot] += m * m * rc;
                }
            }
        }
    }

    // reduce over the 4 lanes of each group (cols), then across the 2 N-warps
#pragma unroll
    for (int slot = 0; slot < 4; ++slot) {
        s1[slot] += __shfl_xor_sync(0xffffffffu, s1[slot], 1);
        s1[slot] += __shfl_xor_sync(0xffffffffu, s1[slot], 2);
        s2[slot] += __shfl_xor_sync(0xffffffffu, s2[slot], 1);
        s2[slot] += __shfl_xor_sync(0xffffffffu, s2[slot], 2);
        s3[slot] += __shfl_xor_sync(0xffffffffu, s3[slot], 1);
        s3[slot] += __shfl_xor_sync(0xffffffffu, s3[slot], 2);
        s4[slot] += __shfl_xor_sync(0xffffffffu, s4[slot], 1);
        s4[slot] += __shfl_xor_sync(0xffffffffu, s4[slot], 2);
    }
    float (*red)[4] = (float(*)[4])(smem + SM_RED);
    __syncthreads();
    if (wn == 0 && tg == 0) {
#pragma unroll
        for (int slot = 0; slot < 4; ++slot) {
            int row = wm * 32 + (slot >> 1) * 16 + (slot & 1) * 8 + g;
            red[row][0] = s1[slot]; red[row][1] = s2[slot];
            red[row][2] = s3[slot]; red[row][3] = s4[slot];
        }
    }
    __syncthreads();
    if (wn == 1 && tg == 0) {
#pragma unroll
        for (int slot = 0; slot < 4; ++slot) {
            int row = wm * 32 + (slot >> 1) * 16 + (slot & 1) * 8 + g;
            int grow = r0 + row;
            if (grow < B) {
                g_coefp[set][half][grow][0] = red[row][0] + s1[slot];
                g_coefp[set][half][grow][1] = red[row][1] + s2[slot];
                g_coefp[set][half][grow][2] = red[row][2] + s3[slot];
                g_coefp[set][half][grow][3] = red[row][3] + s4[slot];
            }
        }
    }
}

// ---------------- Threefry-2x32-20 (exact JAX schedule) ----------------
__device__ __forceinline__ void threefry(uint32_t k0, uint32_t k1,
                                         uint32_t x0, uint32_t x1,
                                         uint32_t& o0, uint32_t& o1) {
    uint32_t ks2 = k0 ^ k1 ^ 0x1BD11BDAu;
    x0 += k0; x1 += k1;
#define TF_RND(r) { x0 += x1; x1 = (x1 << (r)) | (x1 >> (32 - (r))); x1 ^= x0; }
    TF_RND(13) TF_RND(15) TF_RND(26) TF_RND(6)
    x0 += k1;  x1 += ks2 + 1u;
    TF_RND(17) TF_RND(29) TF_RND(16) TF_RND(24)
    x0 += ks2; x1 += k0 + 2u;
    TF_RND(13) TF_RND(15) TF_RND(26) TF_RND(6)
    x0 += k0;  x1 += k1 + 3u;
    TF_RND(17) TF_RND(29) TF_RND(16) TF_RND(24)
    x0 += k1;  x1 += ks2 + 4u;
    TF_RND(13) TF_RND(15) TF_RND(26) TF_RND(6)
    x0 += ks2; x1 += k0 + 5u;
#undef TF_RND
    o0 = x0; o1 = x1;
}

__device__ __forceinline__ float bits_to_unit(uint32_t bits) {
    float f = __uint_as_float((bits >> 9) | 0x3f800000u) - 1.0f;
    return fmaxf(f, 0.0f);
}

// ---------------- per-row rejection sampling (JAX threefry, partitionable mode) ----------------
__global__ void sample_kernel(float* __restrict__ out, int B, float invH)
{
    int i = blockIdx.x * blockDim.x + threadIdx.x;
    if (i >= B) return;

    float s1x = g_coefp[0][0][i][0] + g_coefp[0][1][i][0];
    float s2x = g_coefp[0][0][i][1] + g_coefp[0][1][i][1];
    float s3x = g_coefp[0][0][i][2] + g_coefp[0][1][i][2];
    float s4x = g_coefp[0][0][i][3] + g_coefp[0][1][i][3];
    float s1y = g_coefp[1][0][i][0] + g_coefp[1][1][i][0];
    float s2y = g_coefp[1][0][i][1] + g_coefp[1][1][i][1];
    float s3y = g_coefp[1][0][i][2] + g_coefp[1][1][i][2];
    float s4y = g_coefp[1][0][i][3] + g_coefp[1][1][i][3];

    float ax = 0.5f * (s1x + s4x) * invH;
    float bxc = -s3x * invH;
    float cx = 0.5f * s2x * invH;
    float ay = 0.5f * (s1y + s4y) * invH;
    float byc = -s3y * invH;
    float cy = 0.5f * s2y * invH;

    uint32_t k0, k1;
    threefry(0u, 42u, 0u, (uint32_t)i, k0, k1);

    float xi = 0.0f;
    for (int it = 0; it < 4096; ++it) {
        uint32_t n0, n1, p0, p1, q0, q1;
        threefry(k0, k1, 0u, 0u, n0, n1);
        threefry(k0, k1, 0u, 1u, p0, p1);
        threefry(k0, k1, 0u, 2u, q0, q1);
        uint32_t ub0, ub1, xb0, xb1;
        threefry(p0, p1, 0u, 0u, ub0, ub1);
        threefry(q0, q1, 0u, 0u, xb0, xb1);
        float u  = bits_to_unit(ub0 ^ ub1);
        float x2 = bits_to_unit(xb0 ^ xb1);
        xi = 2.0f * x2 - 1.0f;

        float qx = fmaf(fmaf(cx, xi, bxc), xi, ax);
        float qy = fmaf(fmaf(cy, xi, byc), xi, ay);
        float q  = qx * qy;

        k0 = n0; k1 = n1;
        if (u >= q) break;
    }
    out[i] = fminf(fmaxf(xi, 1e-5f), 10.0f);
}

// ---------------- launch ----------------
extern "C" void kernel_launch(void* const* d_in, const int* in_sizes, int n_in,
                              void* d_out, int out_size)
{
    const float* x   = (const float*)d_in[0];
    const float* y   = (const float*)d_in[1];
    const float* Wmx = (const float*)d_in[2];
    const float* bmx = (const float*)d_in[3];
    const float* Wsx = (const float*)d_in[4];
    const float* bsx = (const float*)d_in[5];
    const float* Wmy = (const float*)d_in[6];
    const float* bmy = (const float*)d_in[7];
    const float* Wsy = (const float*)d_in[8];
    const float* bsy = (const float*)d_in[9];

    int H  = in_sizes[3];
    int IN = in_sizes[2] / H;
    int B  = in_sizes[0] / IN;

    int a4 = (B * IN) / 4;
    int w4 = (H * IN) / 4;
    int total = 2 * a4 + 4 * w4;
    split_all<<<(total + 255) / 256, 256>>>(x, y, Wmx, Wsx, Wmy, Wsy, a4, w4);

    cudaFuncSetAttribute(coef_mma_kernel, cudaFuncAttributeMaxDynamicSharedMemorySize, SMEM_TOTAL);
    dim3 grid(B / MT, 2, NSPLIT);
    coef_mma_kernel<<<grid, 256, SMEM_TOTAL>>>(bmx, bsx, bmy, bsy, B, IN, H);

    sample_kernel<<<(B + 127) / 128, 128>>>((float*)d_out, B, 1.0f / (float)H);
}